// round 2
// baseline (speedup 1.0000x reference)
#include <cuda_runtime.h>
#include <cstdint>

// RecallLoss: input [N=8, C=21, H=512, W=512] f32, target [N, H, W] int64 (or int32 if
// the reference was dumped with JAX x64 disabled — detected at runtime).
// loss = 1 - mean_{n,c} (tp[n,c] + eps) / (tt[n,c] + eps)
//   tp[n,c] = #{l : argmax_c' input[n,c',l] == target[n,l] == c}
//   tt[n,c] = #{l : target[n,l] == c}

#define SMOOTH 1e-5f

constexpr int N_IMG  = 8;
constexpr int C_CLS  = 21;
constexpr int HW     = 512 * 512;       // 262144 positions per image
constexpr int NC     = N_IMG * C_CLS;   // 168 bins
constexpr int TPB    = 256;             // threads per block
constexpr int IPT    = 4;               // positions per thread (float4)
constexpr int BLKS_PER_IMG = HW / (TPB * IPT);   // 256
constexpr int NWARP  = TPB / 32;        // 8

__device__ int g_tp[NC];
__device__ int g_tt[NC];
__device__ int g_is64;

// ---------------------------------------------------------------------------
// Prologue: zero counters + detect target dtype (int64 vs int32).
// int64 targets in [0,21) => every odd 32-bit word is 0. For int32 targets the
// odds of 64 consecutive odd words all being 0 is (1/21)^64 ~ 0.
// Deterministic for fixed inputs -> graph/replay safe.
// ---------------------------------------------------------------------------
__global__ void prologue_kernel(const int* __restrict__ tgt_words) {
    int i = threadIdx.x;
    if (i < NC) { g_tp[i] = 0; g_tt[i] = 0; }
    if (i == 0) {
        int is64 = 1;
        #pragma unroll 1
        for (int k = 0; k < 64; k++) {
            if (tgt_words[2 * k + 1] != 0) { is64 = 0; break; }
        }
        g_is64 = is64;
    }
}

// ---------------------------------------------------------------------------
// Main streaming kernel: argmax over 21 channels + class counting.
// Grid: N_IMG * BLKS_PER_IMG = 2048 blocks of 256 threads, 4 positions/thread.
// All bulk loads use __ldcs (evict-first): data is touched exactly once, so
// keep it out of L2's retained set.
// ---------------------------------------------------------------------------
__global__ __launch_bounds__(TPB) void count_kernel(
    const float* __restrict__ inp, const void* __restrict__ tgt_raw)
{
    __shared__ int s_tp[NWARP][C_CLS];
    __shared__ int s_tt[NWARP][C_CLS];

    const int wid = threadIdx.x >> 5;
    const int lid = threadIdx.x & 31;
    if (lid < C_CLS) { s_tp[wid][lid] = 0; s_tt[wid][lid] = 0; }
    __syncthreads();

    const int n   = blockIdx.x >> 8;         // BLKS_PER_IMG = 256
    const int blk = blockIdx.x & 255;
    const long long l0 = (long long)blk * (TPB * IPT) + threadIdx.x * IPT;

    const float* base = inp + (long long)n * C_CLS * HW + l0;

    // Channel 0 initializes the running argmax (first-index tie semantics via
    // strict >, matching jnp.argmax).
    float4 v = __ldcs(reinterpret_cast<const float4*>(base));
    float m0 = v.x, m1 = v.y, m2 = v.z, m3 = v.w;
    int   i0 = 0,  i1 = 0,  i2 = 0,  i3 = 0;

    #pragma unroll
    for (int c = 1; c < C_CLS; c++) {
        float4 u = __ldcs(reinterpret_cast<const float4*>(base + (long long)c * HW));
        if (u.x > m0) { m0 = u.x; i0 = c; }
        if (u.y > m1) { m1 = u.y; i1 = c; }
        if (u.z > m2) { m2 = u.z; i2 = c; }
        if (u.w > m3) { m3 = u.w; i3 = c; }
    }

    int t0, t1, t2, t3;
    if (g_is64) {
        const long long* tp = (const long long*)tgt_raw + (long long)n * HW + l0;
        longlong2 a = __ldcs(reinterpret_cast<const longlong2*>(tp));
        longlong2 b = __ldcs(reinterpret_cast<const longlong2*>(tp + 2));
        t0 = (int)a.x; t1 = (int)a.y; t2 = (int)b.x; t3 = (int)b.y;
    } else {
        const int* tp = (const int*)tgt_raw + (long long)n * HW + l0;
        int4 a = __ldcs(reinterpret_cast<const int4*>(tp));
        t0 = a.x; t1 = a.y; t2 = a.z; t3 = a.w;
    }

    atomicAdd(&s_tt[wid][t0], 1); if (i0 == t0) atomicAdd(&s_tp[wid][t0], 1);
    atomicAdd(&s_tt[wid][t1], 1); if (i1 == t1) atomicAdd(&s_tp[wid][t1], 1);
    atomicAdd(&s_tt[wid][t2], 1); if (i2 == t2) atomicAdd(&s_tp[wid][t2], 1);
    atomicAdd(&s_tt[wid][t3], 1); if (i3 == t3) atomicAdd(&s_tp[wid][t3], 1);

    __syncthreads();

    if (threadIdx.x < C_CLS) {
        int tp_sum = 0, tt_sum = 0;
        #pragma unroll
        for (int w = 0; w < NWARP; w++) {
            tp_sum += s_tp[w][threadIdx.x];
            tt_sum += s_tt[w][threadIdx.x];
        }
        atomicAdd(&g_tp[n * C_CLS + threadIdx.x], tp_sum);
        atomicAdd(&g_tt[n * C_CLS + threadIdx.x], tt_sum);
    }
}

// ---------------------------------------------------------------------------
// Epilogue: recall per bin, mean, 1 - mean.
// ---------------------------------------------------------------------------
__global__ void final_kernel(float* __restrict__ out) {
    __shared__ float ssum[NWARP];
    const int i = threadIdx.x;
    float r = 0.0f;
    if (i < NC) {
        r = ((float)g_tp[i] + SMOOTH) / ((float)g_tt[i] + SMOOTH);
    }
    #pragma unroll
    for (int o = 16; o > 0; o >>= 1) r += __shfl_down_sync(0xffffffffu, r, o);
    if ((i & 31) == 0) ssum[i >> 5] = r;
    __syncthreads();
    if (i == 0) {
        float s = 0.0f;
        #pragma unroll
        for (int w = 0; w < NWARP; w++) s += ssum[w];
        out[0] = 1.0f - s / (float)NC;
    }
}

extern "C" void kernel_launch(void* const* d_in, const int* in_sizes, int n_in,
                              void* d_out, int out_size) {
    const float* inp = (const float*)d_in[0];
    const void*  tgt = d_in[1];
    float* out = (float*)d_out;

    prologue_kernel<<<1, 256>>>((const int*)tgt);
    count_kernel<<<N_IMG * BLKS_PER_IMG, TPB>>>(inp, tgt);
    final_kernel<<<1, 256>>>(out);
}

// round 3
// speedup vs baseline: 1.0540x; 1.0540x over previous
#include <cuda_runtime.h>
#include <cstdint>

// RecallLoss: input [N=8, C=21, H=512, W=512] f32, target [N, H, W] int64 (or
// int32 if JAX x64 was off when the reference dumped inputs — detected per
// block from the first 16 odd 32-bit words of target).
// loss = 1 - mean_{n,c} (tp[n,c] + eps) / (tt[n,c] + eps)
//
// Single fused kernel: streaming argmax+count, last-block epilogue computes the
// scalar and resets all __device__ state for the next graph replay.

#define SMOOTH 1e-5f

constexpr int N_IMG  = 8;
constexpr int C_CLS  = 21;
constexpr int HW     = 512 * 512;       // 262144 positions per image
constexpr int NC     = N_IMG * C_CLS;   // 168 bins
constexpr int TPB    = 256;
constexpr int IPT    = 4;               // positions per thread (float4)
constexpr int BLKS_PER_IMG = HW / (TPB * IPT);   // 256
constexpr int GRID   = N_IMG * BLKS_PER_IMG;     // 2048
constexpr int NWARP  = TPB / 32;        // 8

// Zero-initialized at module load; the finishing block re-zeroes after each
// launch, so every graph replay starts from a clean state. No prologue needed.
__device__ int g_tp[NC];
__device__ int g_tt[NC];
__device__ unsigned int g_arrive;

__global__ __launch_bounds__(TPB) void recall_fused_kernel(
    const float* __restrict__ inp, const void* __restrict__ tgt_raw,
    float* __restrict__ out)
{
    __shared__ int s_tp[NWARP][C_CLS];
    __shared__ int s_tt[NWARP][C_CLS];
    __shared__ int s_is64;
    __shared__ float s_red[NWARP];

    const int wid = threadIdx.x >> 5;
    const int lid = threadIdx.x & 31;
    if (lid < C_CLS) { s_tp[wid][lid] = 0; s_tt[wid][lid] = 0; }

    // dtype detect: int64 targets in [0,21) have all-zero odd words. For int32
    // the chance 16 specific odd-index values are all 0 is (1/21)^16 ~ 0.
    if (threadIdx.x == 0) {
        const int* w = (const int*)tgt_raw;
        int is64 = 1;
        #pragma unroll
        for (int k = 0; k < 16; k++) is64 &= (w[2 * k + 1] == 0);
        s_is64 = is64;
    }
    __syncthreads();

    const int n   = blockIdx.x >> 8;         // BLKS_PER_IMG = 256
    const int blk = blockIdx.x & 255;
    const long long l0 = (long long)blk * (TPB * IPT) + threadIdx.x * IPT;

    const float* base = inp + (long long)n * C_CLS * HW + l0;

    // Channel 0 seeds the running argmax; strict > keeps the first max index,
    // matching jnp.argmax tie semantics. __ldcs: single-touch streaming data.
    float4 v = __ldcs(reinterpret_cast<const float4*>(base));
    float m0 = v.x, m1 = v.y, m2 = v.z, m3 = v.w;
    int   i0 = 0,  i1 = 0,  i2 = 0,  i3 = 0;

    #pragma unroll
    for (int c = 1; c < C_CLS; c++) {
        float4 u = __ldcs(reinterpret_cast<const float4*>(base + (long long)c * HW));
        if (u.x > m0) { m0 = u.x; i0 = c; }
        if (u.y > m1) { m1 = u.y; i1 = c; }
        if (u.z > m2) { m2 = u.z; i2 = c; }
        if (u.w > m3) { m3 = u.w; i3 = c; }
    }

    int t0, t1, t2, t3;
    if (s_is64) {
        const long long* tp = (const long long*)tgt_raw + (long long)n * HW + l0;
        longlong2 a = __ldcs(reinterpret_cast<const longlong2*>(tp));
        longlong2 b = __ldcs(reinterpret_cast<const longlong2*>(tp + 2));
        t0 = (int)a.x; t1 = (int)a.y; t2 = (int)b.x; t3 = (int)b.y;
    } else {
        const int* tp = (const int*)tgt_raw + (long long)n * HW + l0;
        int4 a = __ldcs(reinterpret_cast<const int4*>(tp));
        t0 = a.x; t1 = a.y; t2 = a.z; t3 = a.w;
    }

    atomicAdd(&s_tt[wid][t0], 1); if (i0 == t0) atomicAdd(&s_tp[wid][t0], 1);
    atomicAdd(&s_tt[wid][t1], 1); if (i1 == t1) atomicAdd(&s_tp[wid][t1], 1);
    atomicAdd(&s_tt[wid][t2], 1); if (i2 == t2) atomicAdd(&s_tp[wid][t2], 1);
    atomicAdd(&s_tt[wid][t3], 1); if (i3 == t3) atomicAdd(&s_tp[wid][t3], 1);

    __syncthreads();

    if (threadIdx.x < C_CLS) {
        int tp_sum = 0, tt_sum = 0;
        #pragma unroll
        for (int w = 0; w < NWARP; w++) {
            tp_sum += s_tp[w][threadIdx.x];
            tt_sum += s_tt[w][threadIdx.x];
        }
        atomicAdd(&g_tp[n * C_CLS + threadIdx.x], tp_sum);
        atomicAdd(&g_tt[n * C_CLS + threadIdx.x], tt_sum);
    }

    // ---- last-block epilogue -------------------------------------------
    __shared__ int s_last;
    __threadfence();   // order this block's global atomics before the arrival
    if (threadIdx.x == 0) {
        unsigned int old = atomicAdd(&g_arrive, 1u);
        s_last = (old == (unsigned int)(GRID - 1));
    }
    __syncthreads();
    if (!s_last) return;

    __threadfence();   // acquire: see every block's counter contributions
    const int i = threadIdx.x;
    float r = 0.0f;
    if (i < NC) {
        r = ((float)g_tp[i] + SMOOTH) / ((float)g_tt[i] + SMOOTH);
    }
    #pragma unroll
    for (int o = 16; o > 0; o >>= 1) r += __shfl_down_sync(0xffffffffu, r, o);
    if (lid == 0) s_red[wid] = r;
    __syncthreads();
    if (i == 0) {
        float s = 0.0f;
        #pragma unroll
        for (int w = 0; w < NWARP; w++) s += s_red[w];
        out[0] = 1.0f - s / (float)NC;
    }

    // Reset state for the next graph replay.
    if (i < NC) { g_tp[i] = 0; g_tt[i] = 0; }
    if (i == 0) g_arrive = 0u;
}

extern "C" void kernel_launch(void* const* d_in, const int* in_sizes, int n_in,
                              void* d_out, int out_size) {
    const float* inp = (const float*)d_in[0];
    const void*  tgt = d_in[1];
    float* out = (float*)d_out;

    recall_fused_kernel<<<GRID, TPB>>>(inp, tgt, out);
}